// round 14
// baseline (speedup 1.0000x reference)
#include <cuda_runtime.h>
#include <cuda_fp16.h>
#include <cstdint>
#include <math.h>

#define Bv   1024
#define Tv   128
#define Dv   128
#define Hv   4
#define HDv  32
#define FFv  512
#define BT   (Bv*Tv)
#define SCALE 0.08838834764831845f            // 128^-0.5
#define SCALE2 0.12751744154070867f           // SCALE * log2(e), for exp2f softmax

// ---------------- scratch (device globals) ----------------
__device__ __align__(256) __half g_q16 [BT*Dv];
__device__ __align__(256) __half g_k16 [BT*Dv];
__device__ __align__(256) __half g_v16 [BT*Dv];
__device__ __align__(256) float  g_x2  [BT*Dv];
__device__ __align__(256) __half g_wq16[Dv*Dv];
__device__ __align__(256) __half g_wk16[Dv*Dv];
__device__ __align__(256) __half g_wv16[Dv*Dv];
__device__ __align__(256) __half g_wo16[Dv*Dv];
__device__ __align__(256) __half g_w116[FFv*Dv];
__device__ __align__(256) __half g_w216[Dv*FFv];

// ---------------- PTX helpers ----------------
__device__ __forceinline__ uint32_t smem_u32(const void* p) {
    uint32_t a;
    asm("{ .reg .u64 t; cvta.to.shared.u64 t, %1; cvt.u32.u64 %0, t; }" : "=r"(a) : "l"(p));
    return a;
}
__device__ __forceinline__ void cp16(uint32_t dst, const void* src) {
    asm volatile("cp.async.cg.shared.global [%0], [%1], 16;" :: "r"(dst), "l"(src));
}
__device__ __forceinline__ void ldsm4(uint32_t (&r)[4], uint32_t addr) {
    asm volatile("ldmatrix.sync.aligned.m8n8.x4.shared.b16 {%0,%1,%2,%3}, [%4];"
        : "=r"(r[0]), "=r"(r[1]), "=r"(r[2]), "=r"(r[3]) : "r"(addr));
}
__device__ __forceinline__ void ldsm4t(uint32_t (&r)[4], uint32_t addr) {
    asm volatile("ldmatrix.sync.aligned.m8n8.x4.trans.shared.b16 {%0,%1,%2,%3}, [%4];"
        : "=r"(r[0]), "=r"(r[1]), "=r"(r[2]), "=r"(r[3]) : "r"(addr));
}
__device__ __forceinline__ void stsm4(uint32_t addr, uint32_t r0, uint32_t r1,
                                      uint32_t r2, uint32_t r3) {
    asm volatile("stmatrix.sync.aligned.m8n8.x4.shared.b16 [%0], {%1,%2,%3,%4};"
        :: "r"(addr), "r"(r0), "r"(r1), "r"(r2), "r"(r3) : "memory");
}
__device__ __forceinline__ void mma_f16(float* c,
    uint32_t a0, uint32_t a1, uint32_t a2, uint32_t a3, uint32_t b0, uint32_t b1)
{
    asm volatile(
        "mma.sync.aligned.m16n8k16.row.col.f32.f16.f16.f32 "
        "{%0,%1,%2,%3}, {%4,%5,%6,%7}, {%8,%9}, {%0,%1,%2,%3};"
        : "+f"(c[0]), "+f"(c[1]), "+f"(c[2]), "+f"(c[3])
        : "r"(a0), "r"(a1), "r"(a2), "r"(a3), "r"(b0), "r"(b1));
}
__device__ __forceinline__ uint32_t h2u(float a, float b) {
    __half2 h = __floats2half2_rn(a, b);
    return *(uint32_t*)&h;
}

// epilogue functors
struct OpNone {
    __device__ __forceinline__ void operator()(float&, float&, float&, float&, int) const {}
};
struct OpBiasRelu {
    const float* b1b;
    __device__ __forceinline__ void operator()(float& v0, float& v1, float& v2,
                                               float& v3, int col) const {
        float2 bb = *(const float2*)(b1b + col);
        v0 = fmaxf(v0 + bb.x, 0.f); v1 = fmaxf(v1 + bb.y, 0.f);
        v2 = fmaxf(v2 + bb.x, 0.f); v3 = fmaxf(v3 + bb.y, 0.f);
    }
};

// ---------------- weight fp32 -> fp16 conversion ----------------
__global__ void cvt6(const float* __restrict__ wq, const float* __restrict__ wk,
                     const float* __restrict__ wv, const float* __restrict__ wo,
                     const float* __restrict__ w1, const float* __restrict__ w2)
{
    const float* src; __half* dst; int n;
    switch (blockIdx.y) {
        case 0: src = wq; dst = g_wq16; n = Dv*Dv;  break;
        case 1: src = wk; dst = g_wk16; n = Dv*Dv;  break;
        case 2: src = wv; dst = g_wv16; n = Dv*Dv;  break;
        case 3: src = wo; dst = g_wo16; n = Dv*Dv;  break;
        case 4: src = w1; dst = g_w116; n = FFv*Dv; break;
        default: src = w2; dst = g_w216; n = Dv*FFv; break;
    }
    for (int i = blockIdx.x * blockDim.x + threadIdx.x; i < n; i += gridDim.x * blockDim.x)
        dst[i] = __float2half_rn(src[i]);
}

// ============ shared pieces (tiles half[.][136], row stride 272B) ==========
struct Frag { int g8, sel, hi, eg, et, mBase, nBase; };
__device__ __forceinline__ Frag mkfrag(int tid) {
    Frag f;
    int lane = tid & 31, wid = tid >> 5;
    f.g8 = lane & 7; f.sel = (lane >> 3) & 1; f.hi = lane >> 4;
    f.eg = lane >> 2; f.et = lane & 3;
    f.mBase = (wid >> 2) * 64; f.nBase = (wid & 3) * 32;
    return f;
}
__device__ __forceinline__ Frag mkfrag64(int tid) {
    Frag f;
    int lane = tid & 31, wid = tid >> 5;
    f.g8 = lane & 7; f.sel = (lane >> 3) & 1; f.hi = lane >> 4;
    f.eg = lane >> 2; f.et = lane & 3;
    f.mBase = (wid >> 2) * 32; f.nBase = (wid & 3) * 32;
    return f;
}

__device__ __forceinline__ void g128_mma(uint32_t sb, uint32_t aoff, uint32_t woff,
                                         const Frag& f, float c[4][4][4])
{
    uint32_t aBase = sb + aoff + ((f.mBase + f.g8 + f.sel * 8) * 136 + f.hi * 8) * 2;
    uint32_t bBase = sb + woff + ((f.nBase + f.g8 + f.hi * 8) * 136 + f.sel * 8) * 2;
    #pragma unroll
    for (int ks = 0; ks < 8; ks++) {
        uint32_t a[4][4];
        #pragma unroll
        for (int mf = 0; mf < 4; mf++)
            ldsm4(a[mf], aBase + mf * 4352 + ks * 32);
        uint32_t bq[2][4];
        #pragma unroll
        for (int p = 0; p < 2; p++)
            ldsm4(bq[p], bBase + p * 4352 + ks * 32);
        #pragma unroll
        for (int mf = 0; mf < 4; mf++)
            #pragma unroll
            for (int nf = 0; nf < 4; nf++)
                mma_f16(c[mf][nf], a[mf][0], a[mf][1], a[mf][2], a[mf][3],
                        bq[nf >> 1][(nf & 1) * 2], bq[nf >> 1][(nf & 1) * 2 + 1]);
    }
}

__device__ __forceinline__ void g64_mma(uint32_t sb, uint32_t aoff, uint32_t woff,
                                        const Frag& f, float c[2][4][4])
{
    uint32_t aBase = sb + aoff + ((f.mBase + f.g8 + f.sel * 8) * 136 + f.hi * 8) * 2;
    uint32_t bBase = sb + woff + ((f.nBase + f.g8 + f.hi * 8) * 136 + f.sel * 8) * 2;
    #pragma unroll
    for (int ks = 0; ks < 8; ks++) {
        uint32_t a[2][4];
        #pragma unroll
        for (int mf = 0; mf < 2; mf++)
            ldsm4(a[mf], aBase + mf * 4352 + ks * 32);
        uint32_t bq[2][4];
        #pragma unroll
        for (int p = 0; p < 2; p++)
            ldsm4(bq[p], bBase + p * 4352 + ks * 32);
        #pragma unroll
        for (int mf = 0; mf < 2; mf++)
            #pragma unroll
            for (int nf = 0; nf < 4; nf++)
                mma_f16(c[mf][nf], a[mf][0], a[mf][1], a[mf][2], a[mf][3],
                        bq[nf >> 1][(nf & 1) * 2], bq[nf >> 1][(nf & 1) * 2 + 1]);
    }
}

__device__ __forceinline__ void ln_to_smem(char* dsm, const float* __restrict__ X,
    const float* __restrict__ lng, const float* __restrict__ lnb, int rowBase, int tid)
{
    int row = tid >> 1, hf = tid & 1;
    const float* xr = X + (size_t)(rowBase + row) * 128 + hf * 64;
    float s = 0.f, s2 = 0.f;
    #pragma unroll
    for (int i = 0; i < 16; i++) {
        float4 v = *(const float4*)(xr + i * 4);
        s  += v.x + v.y + v.z + v.w;
        s2 += v.x * v.x + v.y * v.y + v.z * v.z + v.w * v.w;
    }
    s  += __shfl_xor_sync(0xffffffffu, s, 1);
    s2 += __shfl_xor_sync(0xffffffffu, s2, 1);
    float mu = s * (1.f / 128.f);
    float rstd = rsqrtf(s2 * (1.f / 128.f) - mu * mu + 1e-5f);
    #pragma unroll
    for (int i = 0; i < 16; i++) {
        float4 v = *(const float4*)(xr + i * 4);
        int col = hf * 64 + i * 4;
        float4 gg = *(const float4*)(lng + col);
        float4 bb = *(const float4*)(lnb + col);
        *(uint32_t*)(dsm + row * 272 + col * 2)     = h2u((v.x - mu) * rstd * gg.x + bb.x,
                                                          (v.y - mu) * rstd * gg.y + bb.y);
        *(uint32_t*)(dsm + row * 272 + col * 2 + 4) = h2u((v.z - mu) * rstd * gg.z + bb.z,
                                                          (v.w - mu) * rstd * gg.w + bb.w);
    }
}

__device__ __forceinline__ void ln64_to_smem(char* dsm, const float* __restrict__ X,
    const float* __restrict__ lng, const float* __restrict__ lnb, int rowBase, int tid)
{
    int row = tid >> 2, qt = tid & 3;
    const float* xr = X + (size_t)(rowBase + row) * 128 + qt * 32;
    float s = 0.f, s2 = 0.f;
    #pragma unroll
    for (int i = 0; i < 8; i++) {
        float4 v = *(const float4*)(xr + i * 4);
        s  += v.x + v.y + v.z + v.w;
        s2 += v.x * v.x + v.y * v.y + v.z * v.z + v.w * v.w;
    }
    s  += __shfl_xor_sync(0xffffffffu, s, 1);
    s  += __shfl_xor_sync(0xffffffffu, s, 2);
    s2 += __shfl_xor_sync(0xffffffffu, s2, 1);
    s2 += __shfl_xor_sync(0xffffffffu, s2, 2);
    float mu = s * (1.f / 128.f);
    float rstd = rsqrtf(s2 * (1.f / 128.f) - mu * mu + 1e-5f);
    #pragma unroll
    for (int i = 0; i < 8; i++) {
        float4 v = *(const float4*)(xr + i * 4);
        int col = qt * 32 + i * 4;
        float4 gg = *(const float4*)(lng + col);
        float4 bb = *(const float4*)(lnb + col);
        *(uint32_t*)(dsm + row * 272 + col * 2)     = h2u((v.x - mu) * rstd * gg.x + bb.x,
                                                          (v.y - mu) * rstd * gg.y + bb.y);
        *(uint32_t*)(dsm + row * 272 + col * 2 + 4) = h2u((v.z - mu) * rstd * gg.z + bb.z,
                                                          (v.w - mu) * rstd * gg.w + bb.w);
    }
}

__device__ __forceinline__ void issue_w(uint32_t sb, uint32_t off,
                                        const __half* __restrict__ W, int ldw, int tid)
{
    #pragma unroll
    for (int i = 0; i < 8; i++) {
        int idx = tid + i * 256;
        int r = idx >> 4, cc = idx & 15;
        cp16(sb + off + r * 272 + cc * 16, W + (size_t)r * ldw + cc * 8);
    }
}

template<int MF, typename OP>
__device__ __forceinline__ void stage_tile(uint32_t sb, uint32_t stoff, const Frag& f,
                                           float c[MF][4][4], OP op)
{
    uint32_t base = sb + stoff + ((f.mBase + f.g8 + f.sel * 8) * 136 + f.nBase + f.hi * 8) * 2;
    #pragma unroll
    for (int mf = 0; mf < MF; mf++) {
        uint32_t pk[4][2];
        #pragma unroll
        for (int nf = 0; nf < 4; nf++) {
            float v0 = c[mf][nf][0], v1 = c[mf][nf][1];
            float v2 = c[mf][nf][2], v3 = c[mf][nf][3];
            op(v0, v1, v2, v3, f.nBase + nf * 8 + 2 * f.et);
            pk[nf][0] = h2u(v0, v1);
            pk[nf][1] = h2u(v2, v3);
        }
        #pragma unroll
        for (int jj = 0; jj < 2; jj++)
            stsm4(base + mf * 4352 + jj * 32,
                  pk[2*jj][0], pk[2*jj][1], pk[2*jj+1][0], pk[2*jj+1][1]);
    }
}

// ---------------- fused LN1 + QKV (2 syncs per output) ---------------------
#define QKV_SMEM 104448
__global__ __launch_bounds__(256, 2) void k_qkv3(
    const float* __restrict__ x, const float* __restrict__ g, const float* __restrict__ b)
{
    extern __shared__ char dsm[];
    uint32_t sb = smem_u32(dsm);
    const uint32_t WOFF = 34816, STOFF = 69632;
    int tid = threadIdx.x;
    int rowBase = blockIdx.x * 128;
    Frag f = mkfrag(tid);

    issue_w(sb, WOFF, g_wq16, 128, tid);
    asm volatile("cp.async.commit_group;" ::: "memory");

    ln_to_smem(dsm, x, g, b, rowBase, tid);

    const __half* Wn[2] = { g_wk16, g_wv16 };
    __half* outs[3];
    outs[0] = g_q16; outs[1] = g_k16; outs[2] = g_v16;

    #pragma unroll
    for (int wsel = 0; wsel < 3; wsel++) {
        asm volatile("cp.async.wait_group 0;" ::: "memory");
        __syncthreads();                        // W ready; prev STG of stage done

        float c[4][4][4];
        #pragma unroll
        for (int mf = 0; mf < 4; mf++)
            #pragma unroll
            for (int nf = 0; nf < 4; nf++)
                #pragma unroll
                for (int j = 0; j < 4; j++) c[mf][nf][j] = 0.f;

        g128_mma(sb, 0, WOFF, f, c);
        stage_tile<4>(sb, STOFF, f, c, OpNone());   // own-warp regs -> stage
        __syncthreads();                        // W reads done + stage visible
        if (wsel < 2) {
            issue_w(sb, WOFF, Wn[wsel], 128, tid);  // overlaps the STG phase
            asm volatile("cp.async.commit_group;" ::: "memory");
        }

        __half* C = outs[wsel];
        #pragma unroll
        for (int i = 0; i < 8; i++) {
            int idx = tid + i * 256;
            int r = idx >> 4, c16 = idx & 15;
            uint4 v = *(const uint4*)(dsm + STOFF + r * 272 + c16 * 16);
            *(uint4*)(C + (size_t)(rowBase + r) * 128 + c16 * 8) = v;
        }
    }
}

// ---------------- fused attention (balanced causal) + Wo (unchanged R13) ---
#define ATTNWO_SMEM 104448
__global__ __launch_bounds__(256, 2) void k_attnwo(
    const float* __restrict__ x, const float* __restrict__ bo)
{
    extern __shared__ char dsm[];
    uint32_t sb = smem_u32(dsm);
    const uint32_t VOFF = 34816, AOFF = 69632;
    int b = blockIdx.x;
    int tid = threadIdx.x, lane = tid & 31, w = tid >> 5;
    int g8 = lane & 7, sel = (lane >> 3) & 1, hi8 = (lane >> 4) * 8;
    int eg = lane >> 2, et = lane & 3;
    int tq0 = w * 16;
    size_t base = (size_t)b * Tv * Dv;

    #pragma unroll
    for (int i = 0; i < 8; i++) {
        int idx = tid + i * 256;
        int r = idx >> 4, cc = idx & 15;
        cp16(sb + r * 272 + cc * 16,        g_k16 + base + (size_t)r * 128 + cc * 8);
        cp16(sb + VOFF + r * 272 + cc * 16, g_v16 + base + (size_t)r * 128 + cc * 8);
    }
    asm volatile("cp.async.commit_group;" ::: "memory");
    asm volatile("cp.async.wait_group 0;" ::: "memory");
    __syncthreads();

    const __half* qb = g_q16 + base;

    int ra0 = 8 * w + eg;
    int ra1 = 120 - 8 * w + eg;
    int pN = ((127 - 8 * w) >> 4) + 1;

    #pragma unroll
    for (int hh = 0; hh < 4; hh++) {
        float sacc[16][4];
        #pragma unroll
        for (int cn = 0; cn < 16; cn++)
            #pragma unroll
            for (int j = 0; j < 4; j++) sacc[cn][j] = 0.f;

        #pragma unroll
        for (int ks = 0; ks < 2; ks++) {
            int kc = hh * 32 + ks * 16 + 2 * et;
            uint32_t a0 = *(const uint32_t*)(qb + (size_t)ra0 * 128 + kc);
            uint32_t a1 = *(const uint32_t*)(qb + (size_t)ra1 * 128 + kc);
            uint32_t a2 = *(const uint32_t*)(qb + (size_t)ra0 * 128 + kc + 8);
            uint32_t a3 = *(const uint32_t*)(qb + (size_t)ra1 * 128 + kc + 8);
            #pragma unroll
            for (int p = 0; p < 8; p++) {
                if (p < pN) {
                    uint32_t bq[4];
                    ldsm4(bq, sb + ((p * 16 + g8 + hi8) * 136 + hh * 32 + sel * 8 + ks * 16) * 2);
                    mma_f16(sacc[2 * p],     a0, a1, a2, a3, bq[0], bq[1]);
                    mma_f16(sacc[2 * p + 1], a0, a1, a2, a3, bq[2], bq[3]);
                }
            }
        }

        if (hh == 3) {
            __syncthreads();
            #pragma unroll
            for (int i = 0; i < 8; i++) {
                int idx = tid + i * 256;
                int r = idx >> 4, cc = idx & 15;
                cp16(sb + r * 272 + cc * 16, g_wo16 + (size_t)r * 128 + cc * 8);
            }
            asm volatile("cp.async.commit_group;" ::: "memory");
        }

        #pragma unroll
        for (int cn = 0; cn < 16; cn++) {
            int c0 = cn * 8 + 2 * et;
            sacc[cn][0] = (c0     <= ra0) ? sacc[cn][0] * SCALE2 : -1e30f;
            sacc[cn][1] = (c0 + 1 <= ra0) ? sacc[cn][1] * SCALE2 : -1e30f;
            sacc[cn][2] = (c0     <= ra1) ? sacc[cn][2] * SCALE2 : -1e30f;
            sacc[cn][3] = (c0 + 1 <= ra1) ? sacc[cn][3] * SCALE2 : -1e30f;
        }

        float m0 = -1e30f, m1 = -1e30f;
        #pragma unroll
        for (int cn = 0; cn < 16; cn++) {
            m0 = fmaxf(m0, fmaxf(sacc[cn][0], sacc[cn][1]));
            m1 = fmaxf(m1, fmaxf(sacc[cn][2], sacc[cn][3]));
        }
        m0 = fmaxf(m0, __shfl_xor_sync(0xffffffffu, m0, 1));
        m0 = fmaxf(m0, __shfl_xor_sync(0xffffffffu, m0, 2));
        m1 = fmaxf(m1, __shfl_xor_sync(0xffffffffu, m1, 1));
        m1 = fmaxf(m1, __shfl_xor_sync(0xffffffffu, m1, 2));

        float l0 = 0.f, l1 = 0.f;
        #pragma unroll
        for (int cn = 0; cn < 16; cn++) {
            sacc[cn][0] = exp2f(sacc[cn][0] - m0);
            sacc[cn][1] = exp2f(sacc[cn][1] - m0);
            sacc[cn][2] = exp2f(sacc[cn][2] - m1);
            sacc[cn][3] = exp2f(sacc[cn][3] - m1);
            l0 += sacc[cn][0] + sacc[cn][1];
            l1 += sacc[cn][2] + sacc[cn][3];
        }
        l0 += __shfl_xor_sync(0xffffffffu, l0, 1);
        l0 += __shfl_xor_sync(0xffffffffu, l0, 2);
        l1 += __shfl_xor_sync(0xffffffffu, l1, 1);
        l1 += __shfl_xor_sync(0xffffffffu, l1, 2);
        float inv0 = 1.f / l0, inv1 = 1.f / l1;

        float oacc[4][4];
        #pragma unroll
        for (int nf = 0; nf < 4; nf++)
            #pragma unroll
            for (int j = 0; j < 4; j++) oacc[nf][j] = 0.f;

        #pragma unroll
        for (int ks = 0; ks < 8; ks++) {
            if (ks < pN) {
                uint32_t a0 = h2u(sacc[2*ks][0],   sacc[2*ks][1]);
                uint32_t a1 = h2u(sacc[2*ks][2],   sacc[2*ks][3]);
                uint32_t a2 = h2u(sacc[2*ks+1][0], sacc[2*ks+1][1]);
                uint32_t a3 = h2u(sacc[2*ks+1][2], sacc[2*ks+1][3]);
                #pragma unroll
                for (int nb = 0; nb < 2; nb++) {
                    uint32_t bq[4];
                    ldsm4t(bq, sb + VOFF +
                        ((ks * 16 + g8 + sel * 8) * 136 + hh * 32 + nb * 16 + hi8) * 2);
                    mma_f16(oacc[nb * 2],     a0, a1, a2, a3, bq[0], bq[1]);
                    mma_f16(oacc[nb * 2 + 1], a0, a1, a2, a3, bq[2], bq[3]);
                }
            }
        }

        #pragma unroll
        for (int nf = 0; nf < 4; nf++) {
            int col = hh * 32 + nf * 8 + 2 * et;
            *(uint32_t*)(dsm + AOFF + ((size_t)ra0 * 136 + col) * 2) =
                h2u(oacc[nf][0] * inv0, oacc[nf][1] * inv0);
            *(uint32_t*)(dsm + AOFF + ((size_t)ra1 * 136 + col) * 2) =
                h2u(oacc[nf][2] * inv1, oacc[nf][3] * inv1);
        }
    }

    asm volatile("cp.async.wait_group 0;" ::: "memory");
    __syncthreads();

    float c[16][4];
    #pragma unroll
    for (int nf = 0; nf < 16; nf++)
        #pragma unroll
        for (int j = 0; j < 4; j++) c[nf][j] = 0.f;

    uint32_t aB = sb + AOFF + ((tq0 + g8 + sel * 8) * 136 + hi8) * 2;
    uint32_t bB = sb + ((g8 + hi8) * 136 + sel * 8) * 2;
    #pragma unroll
    for (int ks = 0; ks < 8; ks++) {
        uint32_t a[4];
        ldsm4(a, aB + ks * 32);
        #pragma unroll
        for (int p = 0; p < 8; p++) {
            uint32_t bq[4];
            ldsm4(bq, bB + p * 4352 + ks * 32);
            mma_f16(c[2 * p],     a[0], a[1], a[2], a[3], bq[0], bq[1]);
            mma_f16(c[2 * p + 1], a[0], a[1], a[2], a[3], bq[2], bq[3]);
        }
    }

    int r0 = tq0 + eg, r1 = r0 + 8;
    int grow0 = b * 128 + r0, grow1 = b * 128 + r1;
    #pragma unroll
    for (int nf = 0; nf < 16; nf++) {
        int col = nf * 8 + 2 * et;
        float2 bb = *(const float2*)(bo + col);
        float2 xv0 = *(const float2*)(x + (size_t)grow0 * 128 + col);
        float2 xv1 = *(const float2*)(x + (size_t)grow1 * 128 + col);
        *(float2*)(g_x2 + (size_t)grow0 * 128 + col) =
            make_float2(c[nf][0] + bb.x + xv0.x, c[nf][1] + bb.y + xv0.y);
        *(float2*)(g_x2 + (size_t)grow1 * 128 + col) =
            make_float2(c[nf][2] + bb.x + xv1.x, c[nf][3] + bb.y + xv1.y);
    }
}

// ---------------- fused FFN (M=64, occ 2, 3 syncs/blk) ---------------------
#define FFN_SMEM 104448
__global__ __launch_bounds__(256, 2) void k_ffn64(
    const float* __restrict__ g, const float* __restrict__ b,
    const float* __restrict__ b1, const float* __restrict__ b2,
    float* __restrict__ out)
{
    extern __shared__ char dsm[];
    uint32_t sb = smem_u32(dsm);
    const uint32_t FFO = 17408, W1OFF = 34816, W2OFF = 69632;
    int tid = threadIdx.x;
    int rowBase = blockIdx.x * 64;
    Frag f = mkfrag64(tid);

    issue_w(sb, W1OFF, g_w116, 128, tid);
    asm volatile("cp.async.commit_group;" ::: "memory");
    issue_w(sb, W2OFF, g_w216, 512, tid);
    asm volatile("cp.async.commit_group;" ::: "memory");

    ln64_to_smem(dsm, g_x2, g, b, rowBase, tid);

    float c2[2][4][4];
    #pragma unroll
    for (int mf = 0; mf < 2; mf++)
        #pragma unroll
        for (int nf = 0; nf < 4; nf++)
            #pragma unroll
            for (int j = 0; j < 4; j++) c2[mf][nf][j] = 0.f;

    #pragma unroll
    for (int blk = 0; blk < 4; blk++) {
        asm volatile("cp.async.wait_group 1;" ::: "memory");
        __syncthreads();                 // [S1] W1(blk) ready; A/FF hazards cleared

        float c1[2][4][4];
        #pragma unroll
        for (int mf = 0; mf < 2; mf++)
            #pragma unroll
            for (int nf = 0; nf < 4; nf++)
                #pragma unroll
                for (int j = 0; j < 4; j++) c1[mf][nf][j] = 0.f;
        g64_mma(sb, 0, W1OFF, f, c1);

        // stage own-warp FF rows immediately (no barrier needed: FF readers
        // finished at last blk's S3; other warps' mma1 touch A/W1 only)
        OpBiasRelu op; op.b1b = b1 + blk * 128;
        stage_tile<2>(sb, FFO, f, c1, op);

        asm volatile("cp.async.wait_group 0;" ::: "memory");
        __syncthreads();                 // [S2] W2 ready + FF visible + W1 reads done

        if (blk < 3) {                   // W1(blk+1) load rides under mma2
            issue_w(sb, W1OFF, g_w116 + (size_t)(blk + 1) * 128 * 128, 128, tid);
            asm volatile("cp.async.commit_group;" ::: "memory");
        }

        g64_mma(sb, FFO, W2OFF, f, c2);
        __syncthreads();                 // [S3] W2 + FF reads done

        if (blk < 3) {
            issue_w(sb, W2OFF, g_w216 + (size_t)(blk + 1) * 128, 512, tid);
            asm volatile("cp.async.commit_group;" ::: "memory");
        }
    }

    #pragma unroll
    for (int mf = 0; mf < 2; mf++)
        #pragma unroll
        for (int rr = 0; rr < 2; rr++) {
            int row = rowBase + f.mBase + mf * 16 + f.eg + rr * 8;
            #pragma unroll
            for (int nf = 0; nf < 4; nf++) {
                int col = f.nBase + nf * 8 + 2 * f.et;
                float2 bb = *(const float2*)(b2 + col);
                float2 rv = *(const float2*)(g_x2 + (size_t)row * 128 + col);
                *(float2*)(out + (size_t)row * 128 + col) =
                    make_float2(c2[mf][nf][rr * 2]     + bb.x + rv.x,
                                c2[mf][nf][rr * 2 + 1] + bb.y + rv.y);
            }
        }
}

// ---------------- launch ----------------
extern "C" void kernel_launch(void* const* d_in, const int* in_sizes, int n_in,
                              void* d_out, int out_size)
{
    const float* x     = (const float*)d_in[0];
    const float* ln1_g = (const float*)d_in[1];
    const float* ln1_b = (const float*)d_in[2];
    const float* Wq    = (const float*)d_in[3];
    const float* Wk    = (const float*)d_in[4];
    const float* Wv    = (const float*)d_in[5];
    const float* Wo    = (const float*)d_in[6];
    const float* bo    = (const float*)d_in[7];
    const float* ln2_g = (const float*)d_in[8];
    const float* ln2_b = (const float*)d_in[9];
    const float* W1    = (const float*)d_in[10];
    const float* b1    = (const float*)d_in[11];
    const float* W2    = (const float*)d_in[12];
    const float* b2    = (const float*)d_in[13];
    float* out = (float*)d_out;

    static bool attrs_set = false;
    if (!attrs_set) {
        cudaFuncSetAttribute(k_qkv3,   cudaFuncAttributeMaxDynamicSharedMemorySize, QKV_SMEM);
        cudaFuncSetAttribute(k_attnwo, cudaFuncAttributeMaxDynamicSharedMemorySize, ATTNWO_SMEM);
        cudaFuncSetAttribute(k_ffn64,  cudaFuncAttributeMaxDynamicSharedMemorySize, FFN_SMEM);
        attrs_set = true;
    }

    // 0) weights -> fp16
    cvt6<<<dim3(32, 6), 256>>>(Wq, Wk, Wv, Wo, W1, W2);

    // 1) LN1 + QKV
    k_qkv3<<<BT / 128, 256, QKV_SMEM>>>(x, ln1_g, ln1_b);

    // 2) attention (balanced causal) + Wo + bo + residual -> x2
    k_attnwo<<<Bv, 256, ATTNWO_SMEM>>>(x, bo);

    // 3) LN2 + FFN1 + FFN2 + residual, fused at occ 2
    k_ffn64<<<BT / 64, 256, FFN_SMEM>>>(ln2_g, ln2_b, b1, b2, out);
}

// round 15
// speedup vs baseline: 1.0930x; 1.0930x over previous
#include <cuda_runtime.h>
#include <cuda_fp16.h>
#include <cstdint>
#include <math.h>

#define Bv   1024
#define Tv   128
#define Dv   128
#define Hv   4
#define HDv  32
#define FFv  512
#define BT   (Bv*Tv)
#define SCALE2 0.12751744154070867f           // 128^-0.5 * log2(e)

// ---------------- scratch (device globals) ----------------
__device__ __align__(256) __half g_q16 [BT*Dv];
__device__ __align__(256) float  g_x2  [BT*Dv];
__device__ __align__(256) __half g_wq16[Dv*Dv];
__device__ __align__(256) __half g_wk16[Dv*Dv];
__device__ __align__(256) __half g_wv16[Dv*Dv];
__device__ __align__(256) __half g_wo16[Dv*Dv];
__device__ __align__(256) __half g_w116[FFv*Dv];
__device__ __align__(256) __half g_w216[Dv*FFv];

// ---------------- PTX helpers ----------------
__device__ __forceinline__ uint32_t smem_u32(const void* p) {
    uint32_t a;
    asm("{ .reg .u64 t; cvta.to.shared.u64 t, %1; cvt.u32.u64 %0, t; }" : "=r"(a) : "l"(p));
    return a;
}
__device__ __forceinline__ void cp16(uint32_t dst, const void* src) {
    asm volatile("cp.async.cg.shared.global [%0], [%1], 16;" :: "r"(dst), "l"(src));
}
__device__ __forceinline__ void ldsm4(uint32_t (&r)[4], uint32_t addr) {
    asm volatile("ldmatrix.sync.aligned.m8n8.x4.shared.b16 {%0,%1,%2,%3}, [%4];"
        : "=r"(r[0]), "=r"(r[1]), "=r"(r[2]), "=r"(r[3]) : "r"(addr));
}
__device__ __forceinline__ void ldsm4t(uint32_t (&r)[4], uint32_t addr) {
    asm volatile("ldmatrix.sync.aligned.m8n8.x4.trans.shared.b16 {%0,%1,%2,%3}, [%4];"
        : "=r"(r[0]), "=r"(r[1]), "=r"(r[2]), "=r"(r[3]) : "r"(addr));
}
__device__ __forceinline__ void stsm4(uint32_t addr, uint32_t r0, uint32_t r1,
                                      uint32_t r2, uint32_t r3) {
    asm volatile("stmatrix.sync.aligned.m8n8.x4.shared.b16 [%0], {%1,%2,%3,%4};"
        :: "r"(addr), "r"(r0), "r"(r1), "r"(r2), "r"(r3) : "memory");
}
__device__ __forceinline__ void mma_f16(float* c,
    uint32_t a0, uint32_t a1, uint32_t a2, uint32_t a3, uint32_t b0, uint32_t b1)
{
    asm volatile(
        "mma.sync.aligned.m16n8k16.row.col.f32.f16.f16.f32 "
        "{%0,%1,%2,%3}, {%4,%5,%6,%7}, {%8,%9}, {%0,%1,%2,%3};"
        : "+f"(c[0]), "+f"(c[1]), "+f"(c[2]), "+f"(c[3])
        : "r"(a0), "r"(a1), "r"(a2), "r"(a3), "r"(b0), "r"(b1));
}
__device__ __forceinline__ uint32_t h2u(float a, float b) {
    __half2 h = __floats2half2_rn(a, b);
    return *(uint32_t*)&h;
}

struct OpNone {
    __device__ __forceinline__ void operator()(float&, float&, float&, float&, int) const {}
};
struct OpBiasRelu {
    const float* b1b;
    __device__ __forceinline__ void operator()(float& v0, float& v1, float& v2,
                                               float& v3, int col) const {
        float2 bb = *(const float2*)(b1b + col);
        v0 = fmaxf(v0 + bb.x, 0.f); v1 = fmaxf(v1 + bb.y, 0.f);
        v2 = fmaxf(v2 + bb.x, 0.f); v3 = fmaxf(v3 + bb.y, 0.f);
    }
};

// ---------------- weight fp32 -> fp16 conversion ----------------
__global__ void cvt6(const float* __restrict__ wq, const float* __restrict__ wk,
                     const float* __restrict__ wv, const float* __restrict__ wo,
                     const float* __restrict__ w1, const float* __restrict__ w2)
{
    const float* src; __half* dst; int n;
    switch (blockIdx.y) {
        case 0: src = wq; dst = g_wq16; n = Dv*Dv;  break;
        case 1: src = wk; dst = g_wk16; n = Dv*Dv;  break;
        case 2: src = wv; dst = g_wv16; n = Dv*Dv;  break;
        case 3: src = wo; dst = g_wo16; n = Dv*Dv;  break;
        case 4: src = w1; dst = g_w116; n = FFv*Dv; break;
        default: src = w2; dst = g_w216; n = Dv*FFv; break;
    }
    for (int i = blockIdx.x * blockDim.x + threadIdx.x; i < n; i += gridDim.x * blockDim.x)
        dst[i] = __float2half_rn(src[i]);
}

// ============ shared pieces (tiles half[.][136], row stride 272B) ==========
struct Frag { int g8, sel, hi, eg, et, mBase, nBase; };
__device__ __forceinline__ Frag mkfrag(int tid) {
    Frag f;
    int lane = tid & 31, wid = tid >> 5;
    f.g8 = lane & 7; f.sel = (lane >> 3) & 1; f.hi = lane >> 4;
    f.eg = lane >> 2; f.et = lane & 3;
    f.mBase = (wid >> 2) * 64; f.nBase = (wid & 3) * 32;
    return f;
}
__device__ __forceinline__ Frag mkfrag64(int tid) {
    Frag f;
    int lane = tid & 31, wid = tid >> 5;
    f.g8 = lane & 7; f.sel = (lane >> 3) & 1; f.hi = lane >> 4;
    f.eg = lane >> 2; f.et = lane & 3;
    f.mBase = (wid >> 2) * 32; f.nBase = (wid & 3) * 32;
    return f;
}

__device__ __forceinline__ void g128_mma(uint32_t sb, uint32_t aoff, uint32_t woff,
                                         const Frag& f, float c[4][4][4])
{
    uint32_t aBase = sb + aoff + ((f.mBase + f.g8 + f.sel * 8) * 136 + f.hi * 8) * 2;
    uint32_t bBase = sb + woff + ((f.nBase + f.g8 + f.hi * 8) * 136 + f.sel * 8) * 2;
    #pragma unroll
    for (int ks = 0; ks < 8; ks++) {
        uint32_t a[4][4];
        #pragma unroll
        for (int mf = 0; mf < 4; mf++)
            ldsm4(a[mf], aBase + mf * 4352 + ks * 32);
        uint32_t bq[2][4];
        #pragma unroll
        for (int p = 0; p < 2; p++)
            ldsm4(bq[p], bBase + p * 4352 + ks * 32);
        #pragma unroll
        for (int mf = 0; mf < 4; mf++)
            #pragma unroll
            for (int nf = 0; nf < 4; nf++)
                mma_f16(c[mf][nf], a[mf][0], a[mf][1], a[mf][2], a[mf][3],
                        bq[nf >> 1][(nf & 1) * 2], bq[nf >> 1][(nf & 1) * 2 + 1]);
    }
}

__device__ __forceinline__ void g64_mma(uint32_t sb, uint32_t aoff, uint32_t woff,
                                        const Frag& f, float c[2][4][4])
{
    uint32_t aBase = sb + aoff + ((f.mBase + f.g8 + f.sel * 8) * 136 + f.hi * 8) * 2;
    uint32_t bBase = sb + woff + ((f.nBase + f.g8 + f.hi * 8) * 136 + f.sel * 8) * 2;
    #pragma unroll
    for (int ks = 0; ks < 8; ks++) {
        uint32_t a[2][4];
        #pragma unroll
        for (int mf = 0; mf < 2; mf++)
            ldsm4(a[mf], aBase + mf * 4352 + ks * 32);
        uint32_t bq[2][4];
        #pragma unroll
        for (int p = 0; p < 2; p++)
            ldsm4(bq[p], bBase + p * 4352 + ks * 32);
        #pragma unroll
        for (int mf = 0; mf < 2; mf++)
            #pragma unroll
            for (int nf = 0; nf < 4; nf++)
                mma_f16(c[mf][nf], a[mf][0], a[mf][1], a[mf][2], a[mf][3],
                        bq[nf >> 1][(nf & 1) * 2], bq[nf >> 1][(nf & 1) * 2 + 1]);
    }
}

__device__ __forceinline__ void ln_to_smem(char* dsm, const float* __restrict__ X,
    const float* __restrict__ lng, const float* __restrict__ lnb, int rowBase, int tid)
{
    int row = tid >> 1, hf = tid & 1;
    const float* xr = X + (size_t)(rowBase + row) * 128 + hf * 64;
    float s = 0.f, s2 = 0.f;
    #pragma unroll
    for (int i = 0; i < 16; i++) {
        float4 v = *(const float4*)(xr + i * 4);
        s  += v.x + v.y + v.z + v.w;
        s2 += v.x * v.x + v.y * v.y + v.z * v.z + v.w * v.w;
    }
    s  += __shfl_xor_sync(0xffffffffu, s, 1);
    s2 += __shfl_xor_sync(0xffffffffu, s2, 1);
    float mu = s * (1.f / 128.f);
    float rstd = rsqrtf(s2 * (1.f / 128.f) - mu * mu + 1e-5f);
    #pragma unroll
    for (int i = 0; i < 16; i++) {
        float4 v = *(const float4*)(xr + i * 4);
        int col = hf * 64 + i * 4;
        float4 gg = *(const float4*)(lng + col);
        float4 bb = *(const float4*)(lnb + col);
        *(uint32_t*)(dsm + row * 272 + col * 2)     = h2u((v.x - mu) * rstd * gg.x + bb.x,
                                                          (v.y - mu) * rstd * gg.y + bb.y);
        *(uint32_t*)(dsm + row * 272 + col * 2 + 4) = h2u((v.z - mu) * rstd * gg.z + bb.z,
                                                          (v.w - mu) * rstd * gg.w + bb.w);
    }
}

__device__ __forceinline__ void ln64_to_smem(char* dsm, const float* __restrict__ X,
    const float* __restrict__ lng, const float* __restrict__ lnb, int rowBase, int tid)
{
    int row = tid >> 2, qt = tid & 3;
    const float* xr = X + (size_t)(rowBase + row) * 128 + qt * 32;
    float s = 0.f, s2 = 0.f;
    #pragma unroll
    for (int i = 0; i < 8; i++) {
        float4 v = *(const float4*)(xr + i * 4);
        s  += v.x + v.y + v.z + v.w;
        s2 += v.x * v.x + v.y * v.y + v.z * v.z + v.w * v.w;
    }
    s  += __shfl_xor_sync(0xffffffffu, s, 1);
    s  += __shfl_xor_sync(0xffffffffu, s, 2);
    s2 += __shfl_xor_sync(0xffffffffu, s2, 1);
    s2 += __shfl_xor_sync(0xffffffffu, s2, 2);
    float mu = s * (1.f / 128.f);
    float rstd = rsqrtf(s2 * (1.f / 128.f) - mu * mu + 1e-5f);
    #pragma unroll
    for (int i = 0; i < 8; i++) {
        float4 v = *(const float4*)(xr + i * 4);
        int col = qt * 32 + i * 4;
        float4 gg = *(const float4*)(lng + col);
        float4 bb = *(const float4*)(lnb + col);
        *(uint32_t*)(dsm + row * 272 + col * 2)     = h2u((v.x - mu) * rstd * gg.x + bb.x,
                                                          (v.y - mu) * rstd * gg.y + bb.y);
        *(uint32_t*)(dsm + row * 272 + col * 2 + 4) = h2u((v.z - mu) * rstd * gg.z + bb.z,
                                                          (v.w - mu) * rstd * gg.w + bb.w);
    }
}

__device__ __forceinline__ void issue_w(uint32_t sb, uint32_t off,
                                        const __half* __restrict__ W, int ldw, int tid)
{
    #pragma unroll
    for (int i = 0; i < 8; i++) {
        int idx = tid + i * 256;
        int r = idx >> 4, cc = idx & 15;
        cp16(sb + off + r * 272 + cc * 16, W + (size_t)r * ldw + cc * 8);
    }
}

template<int MF, typename OP>
__device__ __forceinline__ void stage_tile(uint32_t sb, uint32_t stoff, const Frag& f,
                                           float c[MF][4][4], OP op)
{
    uint32_t base = sb + stoff + ((f.mBase + f.g8 + f.sel * 8) * 136 + f.nBase + f.hi * 8) * 2;
    #pragma unroll
    for (int mf = 0; mf < MF; mf++) {
        uint32_t pk[4][2];
        #pragma unroll
        for (int nf = 0; nf < 4; nf++) {
            float v0 = c[mf][nf][0], v1 = c[mf][nf][1];
            float v2 = c[mf][nf][2], v3 = c[mf][nf][3];
            op(v0, v1, v2, v3, f.nBase + nf * 8 + 2 * f.et);
            pk[nf][0] = h2u(v0, v1);
            pk[nf][1] = h2u(v2, v3);
        }
        #pragma unroll
        for (int jj = 0; jj < 2; jj++)
            stsm4(base + mf * 4352 + jj * 32,
                  pk[2*jj][0], pk[2*jj][1], pk[2*jj+1][0], pk[2*jj+1][1]);
    }
}

// ============ mega kernel: LN1 + QKV + causal attention + Wo + residual ====
// One CTA per batch. Regions (each 34816B): R0 @0: LN(x) A -> V;
// R1 @34816: W rotator -> AO; R2 @69632: Q stage -> K -> Wo.
#define QA_SMEM 104448
__global__ __launch_bounds__(256, 2) void k_qkvattn(
    const float* __restrict__ x, const float* __restrict__ lng,
    const float* __restrict__ lnb, const float* __restrict__ bo)
{
    extern __shared__ char dsm[];
    uint32_t sb = smem_u32(dsm);
    const uint32_t R1 = 34816, R2 = 69632;
    int b = blockIdx.x;
    int tid = threadIdx.x, w = tid >> 5;
    Frag f = mkfrag(tid);
    int g8 = f.g8, sel = f.sel, hi8 = f.hi * 8, eg = f.eg, et = f.et;
    int tq0 = w * 16;
    int rowBase = b * 128;
    size_t base = (size_t)rowBase * 128;

    issue_w(sb, R1, g_wq16, 128, tid);
    asm volatile("cp.async.commit_group;" ::: "memory");
    ln_to_smem(dsm, x, lng, lnb, rowBase, tid);

    // ---- Q: LN(x) @ Wq^T -> stage R2 -> gmem (L2-warm for frag reload) ----
    asm volatile("cp.async.wait_group 0;" ::: "memory");
    __syncthreads();
    {
        float c[4][4][4];
        #pragma unroll
        for (int mf = 0; mf < 4; mf++)
            #pragma unroll
            for (int nf = 0; nf < 4; nf++)
                #pragma unroll
                for (int j = 0; j < 4; j++) c[mf][nf][j] = 0.f;
        g128_mma(sb, 0, R1, f, c);
        stage_tile<4>(sb, R2, f, c, OpNone());
        __syncthreads();                         // Wq reads done + Q stage visible
        issue_w(sb, R1, g_wk16, 128, tid);       // overlaps q-copy
        asm volatile("cp.async.commit_group;" ::: "memory");
        #pragma unroll
        for (int i = 0; i < 8; i++) {
            int idx = tid + i * 256;
            int r = idx >> 4, c16 = idx & 15;
            uint4 v = *(const uint4*)(dsm + R2 + r * 272 + c16 * 16);
            *(uint4*)(g_q16 + base + (size_t)r * 128 + c16 * 8) = v;
        }
    }

    // ---- K: LN(x) @ Wk^T -> stays in R2 ----
    asm volatile("cp.async.wait_group 0;" ::: "memory");
    __syncthreads();                             // Wk ready; q-copy reads of R2 done
    {
        float c[4][4][4];
        #pragma unroll
        for (int mf = 0; mf < 4; mf++)
            #pragma unroll
            for (int nf = 0; nf < 4; nf++)
                #pragma unroll
                for (int j = 0; j < 4; j++) c[mf][nf][j] = 0.f;
        g128_mma(sb, 0, R1, f, c);
        stage_tile<4>(sb, R2, f, c, OpNone());   // K into R2
        __syncthreads();                         // Wk reads done; K visible
        issue_w(sb, R1, g_wv16, 128, tid);
        asm volatile("cp.async.commit_group;" ::: "memory");
    }

    // ---- V: LN(x) @ Wv^T -> stays in R0 (overwrites A) ----
    asm volatile("cp.async.wait_group 0;" ::: "memory");
    __syncthreads();
    {
        float c[4][4][4];
        #pragma unroll
        for (int mf = 0; mf < 4; mf++)
            #pragma unroll
            for (int nf = 0; nf < 4; nf++)
                #pragma unroll
                for (int j = 0; j < 4; j++) c[mf][nf][j] = 0.f;
        g128_mma(sb, 0, R1, f, c);
        __syncthreads();                         // all warps' A reads done
        stage_tile<4>(sb, 0, f, c, OpNone());    // V into R0
        __syncthreads();                         // V visible; R1 free for AO
    }

    // ---- attention: Q from gmem, K @ R2, V @ R0, AO @ R1 ----
    const __half* qb = g_q16 + base;
    int ra0 = 8 * w + eg;
    int ra1 = 120 - 8 * w + eg;
    int pN = ((127 - 8 * w) >> 4) + 1;

    #pragma unroll
    for (int hh = 0; hh < 4; hh++) {
        float sacc[16][4];
        #pragma unroll
        for (int cn = 0; cn < 16; cn++)
            #pragma unroll
            for (int j = 0; j < 4; j++) sacc[cn][j] = 0.f;

        #pragma unroll
        for (int ks = 0; ks < 2; ks++) {
            int kc = hh * 32 + ks * 16 + 2 * et;
            uint32_t a0 = *(const uint32_t*)(qb + (size_t)ra0 * 128 + kc);
            uint32_t a1 = *(const uint32_t*)(qb + (size_t)ra1 * 128 + kc);
            uint32_t a2 = *(const uint32_t*)(qb + (size_t)ra0 * 128 + kc + 8);
            uint32_t a3 = *(const uint32_t*)(qb + (size_t)ra1 * 128 + kc + 8);
            #pragma unroll
            for (int p = 0; p < 8; p++) {
                if (p < pN) {
                    uint32_t bq[4];
                    ldsm4(bq, sb + R2 + ((p * 16 + g8 + hi8) * 136 + hh * 32 + sel * 8 + ks * 16) * 2);
                    mma_f16(sacc[2 * p],     a0, a1, a2, a3, bq[0], bq[1]);
                    mma_f16(sacc[2 * p + 1], a0, a1, a2, a3, bq[2], bq[3]);
                }
            }
        }

        if (hh == 3) {                           // K dead: prefetch Wo into R2
            __syncthreads();
            issue_w(sb, R2, g_wo16, 128, tid);
            asm volatile("cp.async.commit_group;" ::: "memory");
        }

        #pragma unroll
        for (int cn = 0; cn < 16; cn++) {
            int c0 = cn * 8 + 2 * et;
            sacc[cn][0] = (c0     <= ra0) ? sacc[cn][0] * SCALE2 : -1e30f;
            sacc[cn][1] = (c0 + 1 <= ra0) ? sacc[cn][1] * SCALE2 : -1e30f;
            sacc[cn][2] = (c0     <= ra1) ? sacc[cn][2] * SCALE2 : -1e30f;
            sacc[cn][3] = (c0 + 1 <= ra1) ? sacc[cn][3] * SCALE2 : -1e30f;
        }

        float m0 = -1e30f, m1 = -1e30f;
        #pragma unroll
        for (int cn = 0; cn < 16; cn++) {
            m0 = fmaxf(m0, fmaxf(sacc[cn][0], sacc[cn][1]));
            m1 = fmaxf(m1, fmaxf(sacc[cn][2], sacc[cn][3]));
        }
        m0 = fmaxf(m0, __shfl_xor_sync(0xffffffffu, m0, 1));
        m0 = fmaxf(m0, __shfl_xor_sync(0xffffffffu, m0, 2));
        m1 = fmaxf(m1, __shfl_xor_sync(0xffffffffu, m1, 1));
        m1 = fmaxf(m1, __shfl_xor_sync(0xffffffffu, m1, 2));

        float l0 = 0.f, l1 = 0.f;
        #pragma unroll
        for (int cn = 0; cn < 16; cn++) {
            sacc[cn][0] = exp2f(sacc[cn][0] - m0);
            sacc[cn][1] = exp2f(sacc[cn][1] - m0);
            sacc[cn][2] = exp2f(sacc[cn][2] - m1);
            sacc[cn][3] = exp2f(sacc[cn][3] - m1);
            l0 += sacc[cn][0] + sacc[cn][1];
            l1 += sacc[cn][2] + sacc[cn][3];
        }
        l0 += __shfl_xor_sync(0xffffffffu, l0, 1);
        l0 += __shfl_xor_sync(0xffffffffu, l0, 2);
        l1 += __shfl_xor_sync(0xffffffffu, l1, 1);
        l1 += __shfl_xor_sync(0xffffffffu, l1, 2);
        float inv0 = 1.f / l0, inv1 = 1.f / l1;

        float oacc[4][4];
        #pragma unroll
        for (int nf = 0; nf < 4; nf++)
            #pragma unroll
            for (int j = 0; j < 4; j++) oacc[nf][j] = 0.f;

        #pragma unroll
        for (int ks = 0; ks < 8; ks++) {
            if (ks < pN) {
                uint32_t a0 = h2u(sacc[2*ks][0],   sacc[2*ks][1]);
                uint32_t a1 = h2u(sacc[2*ks][2],   sacc[2*ks][3]);
                uint32_t a2 = h2u(sacc[2*ks+1][0], sacc[2*ks+1][1]);
                uint32_t a3 = h2u(sacc[2*ks+1][2], sacc[2*ks+1][3]);
                #pragma unroll
                for (int nb = 0; nb < 2; nb++) {
                    uint32_t bq[4];
                    ldsm4t(bq, sb + ((ks * 16 + g8 + sel * 8) * 136 + hh * 32 + nb * 16 + hi8) * 2);
                    mma_f16(oacc[nb * 2],     a0, a1, a2, a3, bq[0], bq[1]);
                    mma_f16(oacc[nb * 2 + 1], a0, a1, a2, a3, bq[2], bq[3]);
                }
            }
        }

        #pragma unroll
        for (int nf = 0; nf < 4; nf++) {
            int col = hh * 32 + nf * 8 + 2 * et;
            *(uint32_t*)(dsm + R1 + ((size_t)ra0 * 136 + col) * 2) =
                h2u(oacc[nf][0] * inv0, oacc[nf][1] * inv0);
            *(uint32_t*)(dsm + R1 + ((size_t)ra1 * 136 + col) * 2) =
                h2u(oacc[nf][2] * inv1, oacc[nf][3] * inv1);
        }
    }

    asm volatile("cp.async.wait_group 0;" ::: "memory");
    __syncthreads();                             // Wo ready + AO visible

    // ---- Wo GEMM: A = AO (R1), B = Wo (R2) ----
    float c[16][4];
    #pragma unroll
    for (int nf = 0; nf < 16; nf++)
        #pragma unroll
        for (int j = 0; j < 4; j++) c[nf][j] = 0.f;

    uint32_t aB = sb + R1 + ((tq0 + g8 + sel * 8) * 136 + hi8) * 2;
    uint32_t bB = sb + R2 + ((g8 + hi8) * 136 + sel * 8) * 2;
    #pragma unroll
    for (int ks = 0; ks < 8; ks++) {
        uint32_t a[4];
        ldsm4(a, aB + ks * 32);
        #pragma unroll
        for (int p = 0; p < 8; p++) {
            uint32_t bq[4];
            ldsm4(bq, bB + p * 4352 + ks * 32);
            mma_f16(c[2 * p],     a[0], a[1], a[2], a[3], bq[0], bq[1]);
            mma_f16(c[2 * p + 1], a[0], a[1], a[2], a[3], bq[2], bq[3]);
        }
    }

    int r0 = tq0 + eg, r1 = r0 + 8;
    int grow0 = rowBase + r0, grow1 = rowBase + r1;
    #pragma unroll
    for (int nf = 0; nf < 16; nf++) {
        int col = nf * 8 + 2 * et;
        float2 bb = *(const float2*)(bo + col);
        float2 xv0 = *(const float2*)(x + (size_t)grow0 * 128 + col);
        float2 xv1 = *(const float2*)(x + (size_t)grow1 * 128 + col);
        *(float2*)(g_x2 + (size_t)grow0 * 128 + col) =
            make_float2(c[nf][0] + bb.x + xv0.x, c[nf][1] + bb.y + xv0.y);
        *(float2*)(g_x2 + (size_t)grow1 * 128 + col) =
            make_float2(c[nf][2] + bb.x + xv1.x, c[nf][3] + bb.y + xv1.y);
    }
}

// ---------------- fused FFN (M=64, occ 2, R13 sync scheme) -----------------
#define FFN_SMEM 104448
__global__ __launch_bounds__(256, 2) void k_ffn64(
    const float* __restrict__ g, const float* __restrict__ b,
    const float* __restrict__ b1, const float* __restrict__ b2,
    float* __restrict__ out)
{
    extern __shared__ char dsm[];
    uint32_t sb = smem_u32(dsm);
    const uint32_t FFO = 17408, W1OFF = 34816, W2OFF = 69632;
    int tid = threadIdx.x;
    int rowBase = blockIdx.x * 64;
    Frag f = mkfrag64(tid);

    issue_w(sb, W1OFF, g_w116, 128, tid);
    asm volatile("cp.async.commit_group;" ::: "memory");
    issue_w(sb, W2OFF, g_w216, 512, tid);
    asm volatile("cp.async.commit_group;" ::: "memory");

    ln64_to_smem(dsm, g_x2, g, b, rowBase, tid);

    float c2[2][4][4];
    #pragma unroll
    for (int mf = 0; mf < 2; mf++)
        #pragma unroll
        for (int nf = 0; nf < 4; nf++)
            #pragma unroll
            for (int j = 0; j < 4; j++) c2[mf][nf][j] = 0.f;

    #pragma unroll
    for (int blk = 0; blk < 4; blk++) {
        asm volatile("cp.async.wait_group 1;" ::: "memory");
        __syncthreads();

        float c1[2][4][4];
        #pragma unroll
        for (int mf = 0; mf < 2; mf++)
            #pragma unroll
            for (int nf = 0; nf < 4; nf++)
                #pragma unroll
                for (int j = 0; j < 4; j++) c1[mf][nf][j] = 0.f;
        g64_mma(sb, 0, W1OFF, f, c1);
        __syncthreads();

        if (blk < 3) {
            issue_w(sb, W1OFF, g_w116 + (size_t)(blk + 1) * 128 * 128, 128, tid);
            asm volatile("cp.async.commit_group;" ::: "memory");
        }

        OpBiasRelu op; op.b1b = b1 + blk * 128;
        stage_tile<2>(sb, FFO, f, c1, op);

        if (blk < 3) asm volatile("cp.async.wait_group 1;" ::: "memory");
        else         asm volatile("cp.async.wait_group 0;" ::: "memory");
        __syncthreads();

        g64_mma(sb, FFO, W2OFF, f, c2);
        __syncthreads();

        if (blk < 3) {
            issue_w(sb, W2OFF, g_w216 + (size_t)(blk + 1) * 128, 512, tid);
            asm volatile("cp.async.commit_group;" ::: "memory");
        }
    }

    #pragma unroll
    for (int mf = 0; mf < 2; mf++)
        #pragma unroll
        for (int rr = 0; rr < 2; rr++) {
            int row = rowBase + f.mBase + mf * 16 + f.eg + rr * 8;
            #pragma unroll
            for (int nf = 0; nf < 4; nf++) {
                int col = f.nBase + nf * 8 + 2 * f.et;
                float2 bb = *(const float2*)(b2 + col);
                float2 rv = *(const float2*)(g_x2 + (size_t)row * 128 + col);
                *(float2*)(out + (size_t)row * 128 + col) =
                    make_float2(c2[mf][nf][rr * 2]     + bb.x + rv.x,
                                c2[mf][nf][rr * 2 + 1] + bb.y + rv.y);
            }
        }
}

// ---------------- launch ----------------
extern "C" void kernel_launch(void* const* d_in, const int* in_sizes, int n_in,
                              void* d_out, int out_size)
{
    const float* x     = (const float*)d_in[0];
    const float* ln1_g = (const float*)d_in[1];
    const float* ln1_b = (const float*)d_in[2];
    const float* Wq    = (const float*)d_in[3];
    const float* Wk    = (const float*)d_in[4];
    const float* Wv    = (const float*)d_in[5];
    const float* Wo    = (const float*)d_in[6];
    const float* bo    = (const float*)d_in[7];
    const float* ln2_g = (const float*)d_in[8];
    const float* ln2_b = (const float*)d_in[9];
    const float* W1    = (const float*)d_in[10];
    const float* b1    = (const float*)d_in[11];
    const float* W2    = (const float*)d_in[12];
    const float* b2    = (const float*)d_in[13];
    float* out = (float*)d_out;

    static bool attrs_set = false;
    if (!attrs_set) {
        cudaFuncSetAttribute(k_qkvattn, cudaFuncAttributeMaxDynamicSharedMemorySize, QA_SMEM);
        cudaFuncSetAttribute(k_ffn64,   cudaFuncAttributeMaxDynamicSharedMemorySize, FFN_SMEM);
        attrs_set = true;
    }

    // 0) weights -> fp16
    cvt6<<<dim3(32, 6), 256>>>(Wq, Wk, Wv, Wo, W1, W2);

    // 1) LN1 + QKV + causal attention + Wo + residual -> x2 (one CTA per batch)
    k_qkvattn<<<Bv, 256, QA_SMEM>>>(x, ln1_g, ln1_b, bo);

    // 2) LN2 + FFN1 + FFN2 + residual
    k_ffn64<<<BT / 64, 256, FFN_SMEM>>>(ln2_g, ln2_b, b1, b2, out);
}

// round 16
// speedup vs baseline: 1.1628x; 1.0639x over previous
#include <cuda_runtime.h>
#include <cuda_fp16.h>
#include <cstdint>
#include <math.h>

#define Bv   1024
#define Tv   128
#define Dv   128
#define Hv   4
#define HDv  32
#define FFv  512
#define BT   (Bv*Tv)
#define SCALE2 0.12751744154070867f           // 128^-0.5 * log2(e)

// ---------------- scratch (device globals) ----------------
__device__ __align__(256) __half g_q16 [BT*Dv];
__device__ __align__(256) __half g_h16 [BT*Dv];   // LN2(x2), fp16
__device__ __align__(256) float  g_x2  [BT*Dv];
__device__ __align__(256) __half g_wq16[Dv*Dv];
__device__ __align__(256) __half g_wk16[Dv*Dv];
__device__ __align__(256) __half g_wv16[Dv*Dv];
__device__ __align__(256) __half g_wo16[Dv*Dv];
__device__ __align__(256) __half g_w116[FFv*Dv];
__device__ __align__(256) __half g_w216[Dv*FFv];

// ---------------- PTX helpers ----------------
__device__ __forceinline__ uint32_t smem_u32(const void* p) {
    uint32_t a;
    asm("{ .reg .u64 t; cvta.to.shared.u64 t, %1; cvt.u32.u64 %0, t; }" : "=r"(a) : "l"(p));
    return a;
}
__device__ __forceinline__ void cp16(uint32_t dst, const void* src) {
    asm volatile("cp.async.cg.shared.global [%0], [%1], 16;" :: "r"(dst), "l"(src));
}
__device__ __forceinline__ void ldsm4(uint32_t (&r)[4], uint32_t addr) {
    asm volatile("ldmatrix.sync.aligned.m8n8.x4.shared.b16 {%0,%1,%2,%3}, [%4];"
        : "=r"(r[0]), "=r"(r[1]), "=r"(r[2]), "=r"(r[3]) : "r"(addr));
}
__device__ __forceinline__ void ldsm4t(uint32_t (&r)[4], uint32_t addr) {
    asm volatile("ldmatrix.sync.aligned.m8n8.x4.trans.shared.b16 {%0,%1,%2,%3}, [%4];"
        : "=r"(r[0]), "=r"(r[1]), "=r"(r[2]), "=r"(r[3]) : "r"(addr));
}
__device__ __forceinline__ void stsm4(uint32_t addr, uint32_t r0, uint32_t r1,
                                      uint32_t r2, uint32_t r3) {
    asm volatile("stmatrix.sync.aligned.m8n8.x4.shared.b16 [%0], {%1,%2,%3,%4};"
        :: "r"(addr), "r"(r0), "r"(r1), "r"(r2), "r"(r3) : "memory");
}
__device__ __forceinline__ void mma_f16(float* c,
    uint32_t a0, uint32_t a1, uint32_t a2, uint32_t a3, uint32_t b0, uint32_t b1)
{
    asm volatile(
        "mma.sync.aligned.m16n8k16.row.col.f32.f16.f16.f32 "
        "{%0,%1,%2,%3}, {%4,%5,%6,%7}, {%8,%9}, {%0,%1,%2,%3};"
        : "+f"(c[0]), "+f"(c[1]), "+f"(c[2]), "+f"(c[3])
        : "r"(a0), "r"(a1), "r"(a2), "r"(a3), "r"(b0), "r"(b1));
}
__device__ __forceinline__ uint32_t h2u(float a, float b) {
    __half2 h = __floats2half2_rn(a, b);
    return *(uint32_t*)&h;
}

struct OpNone {
    __device__ __forceinline__ void operator()(float&, float&, float&, float&, int) const {}
};
struct OpBiasRelu {
    const float* b1b;
    __device__ __forceinline__ void operator()(float& v0, float& v1, float& v2,
                                               float& v3, int col) const {
        float2 bb = *(const float2*)(b1b + col);
        v0 = fmaxf(v0 + bb.x, 0.f); v1 = fmaxf(v1 + bb.y, 0.f);
        v2 = fmaxf(v2 + bb.x, 0.f); v3 = fmaxf(v3 + bb.y, 0.f);
    }
};

// ---------------- weight fp32 -> fp16 conversion (vectorized) --------------
__global__ void cvt6(const float* __restrict__ wq, const float* __restrict__ wk,
                     const float* __restrict__ wv, const float* __restrict__ wo,
                     const float* __restrict__ w1, const float* __restrict__ w2)
{
    const float* src; __half* dst; int n4;
    switch (blockIdx.y) {
        case 0: src = wq; dst = g_wq16; n4 = Dv*Dv/4;  break;
        case 1: src = wk; dst = g_wk16; n4 = Dv*Dv/4;  break;
        case 2: src = wv; dst = g_wv16; n4 = Dv*Dv/4;  break;
        case 3: src = wo; dst = g_wo16; n4 = Dv*Dv/4;  break;
        case 4: src = w1; dst = g_w116; n4 = FFv*Dv/4; break;
        default: src = w2; dst = g_w216; n4 = Dv*FFv/4; break;
    }
    int i = blockIdx.x * blockDim.x + threadIdx.x;
    if (i < n4) {
        float4 v = *(const float4*)(src + i * 4);
        uint2 o;
        o.x = h2u(v.x, v.y);
        o.y = h2u(v.z, v.w);
        *(uint2*)(dst + i * 4) = o;
    }
}

// ============ shared pieces (tiles half[.][136], row stride 272B) ==========
struct Frag { int g8, sel, hi, eg, et, mBase, nBase; };
__device__ __forceinline__ Frag mkfrag(int tid) {
    Frag f;
    int lane = tid & 31, wid = tid >> 5;
    f.g8 = lane & 7; f.sel = (lane >> 3) & 1; f.hi = lane >> 4;
    f.eg = lane >> 2; f.et = lane & 3;
    f.mBase = (wid >> 2) * 64; f.nBase = (wid & 3) * 32;
    return f;
}
__device__ __forceinline__ Frag mkfrag64(int tid) {
    Frag f;
    int lane = tid & 31, wid = tid >> 5;
    f.g8 = lane & 7; f.sel = (lane >> 3) & 1; f.hi = lane >> 4;
    f.eg = lane >> 2; f.et = lane & 3;
    f.mBase = (wid >> 2) * 32; f.nBase = (wid & 3) * 32;
    return f;
}

__device__ __forceinline__ void g128_mma(uint32_t sb, uint32_t aoff, uint32_t woff,
                                         const Frag& f, float c[4][4][4])
{
    uint32_t aBase = sb + aoff + ((f.mBase + f.g8 + f.sel * 8) * 136 + f.hi * 8) * 2;
    uint32_t bBase = sb + woff + ((f.nBase + f.g8 + f.hi * 8) * 136 + f.sel * 8) * 2;
    #pragma unroll
    for (int ks = 0; ks < 8; ks++) {
        uint32_t a[4][4];
        #pragma unroll
        for (int mf = 0; mf < 4; mf++)
            ldsm4(a[mf], aBase + mf * 4352 + ks * 32);
        uint32_t bq[2][4];
        #pragma unroll
        for (int p = 0; p < 2; p++)
            ldsm4(bq[p], bBase + p * 4352 + ks * 32);
        #pragma unroll
        for (int mf = 0; mf < 4; mf++)
            #pragma unroll
            for (int nf = 0; nf < 4; nf++)
                mma_f16(c[mf][nf], a[mf][0], a[mf][1], a[mf][2], a[mf][3],
                        bq[nf >> 1][(nf & 1) * 2], bq[nf >> 1][(nf & 1) * 2 + 1]);
    }
}

__device__ __forceinline__ void g64_mma(uint32_t sb, uint32_t aoff, uint32_t woff,
                                        const Frag& f, float c[2][4][4])
{
    uint32_t aBase = sb + aoff + ((f.mBase + f.g8 + f.sel * 8) * 136 + f.hi * 8) * 2;
    uint32_t bBase = sb + woff + ((f.nBase + f.g8 + f.hi * 8) * 136 + f.sel * 8) * 2;
    #pragma unroll
    for (int ks = 0; ks < 8; ks++) {
        uint32_t a[2][4];
        #pragma unroll
        for (int mf = 0; mf < 2; mf++)
            ldsm4(a[mf], aBase + mf * 4352 + ks * 32);
        uint32_t bq[2][4];
        #pragma unroll
        for (int p = 0; p < 2; p++)
            ldsm4(bq[p], bBase + p * 4352 + ks * 32);
        #pragma unroll
        for (int mf = 0; mf < 2; mf++)
            #pragma unroll
            for (int nf = 0; nf < 4; nf++)
                mma_f16(c[mf][nf], a[mf][0], a[mf][1], a[mf][2], a[mf][3],
                        bq[nf >> 1][(nf & 1) * 2], bq[nf >> 1][(nf & 1) * 2 + 1]);
    }
}

__device__ __forceinline__ void ln_to_smem(char* dsm, const float* __restrict__ X,
    const float* __restrict__ lng, const float* __restrict__ lnb, int rowBase, int tid)
{
    int row = tid >> 1, hf = tid & 1;
    const float* xr = X + (size_t)(rowBase + row) * 128 + hf * 64;
    float s = 0.f, s2 = 0.f;
    #pragma unroll
    for (int i = 0; i < 16; i++) {
        float4 v = *(const float4*)(xr + i * 4);
        s  += v.x + v.y + v.z + v.w;
        s2 += v.x * v.x + v.y * v.y + v.z * v.z + v.w * v.w;
    }
    s  += __shfl_xor_sync(0xffffffffu, s, 1);
    s2 += __shfl_xor_sync(0xffffffffu, s2, 1);
    float mu = s * (1.f / 128.f);
    float rstd = rsqrtf(s2 * (1.f / 128.f) - mu * mu + 1e-5f);
    #pragma unroll
    for (int i = 0; i < 16; i++) {
        float4 v = *(const float4*)(xr + i * 4);
        int col = hf * 64 + i * 4;
        float4 gg = *(const float4*)(lng + col);
        float4 bb = *(const float4*)(lnb + col);
        *(uint32_t*)(dsm + row * 272 + col * 2)     = h2u((v.x - mu) * rstd * gg.x + bb.x,
                                                          (v.y - mu) * rstd * gg.y + bb.y);
        *(uint32_t*)(dsm + row * 272 + col * 2 + 4) = h2u((v.z - mu) * rstd * gg.z + bb.z,
                                                          (v.w - mu) * rstd * gg.w + bb.w);
    }
}

__device__ __forceinline__ void issue_w(uint32_t sb, uint32_t off,
                                        const __half* __restrict__ W, int ldw, int tid)
{
    #pragma unroll
    for (int i = 0; i < 8; i++) {
        int idx = tid + i * 256;
        int r = idx >> 4, cc = idx & 15;
        cp16(sb + off + r * 272 + cc * 16, W + (size_t)r * ldw + cc * 8);
    }
}

// cp.async a 64x128-half tile (A for FFN)
__device__ __forceinline__ void issue_a64(uint32_t sb, const __half* __restrict__ A, int tid)
{
    #pragma unroll
    for (int i = 0; i < 4; i++) {
        int idx = tid + i * 256;
        int r = idx >> 4, cc = idx & 15;
        cp16(sb + r * 272 + cc * 16, A + (size_t)r * 128 + cc * 8);
    }
}

template<int MF, typename OP>
__device__ __forceinline__ void stage_tile(uint32_t sb, uint32_t stoff, const Frag& f,
                                           float c[MF][4][4], OP op)
{
    uint32_t base = sb + stoff + ((f.mBase + f.g8 + f.sel * 8) * 136 + f.nBase + f.hi * 8) * 2;
    #pragma unroll
    for (int mf = 0; mf < MF; mf++) {
        uint32_t pk[4][2];
        #pragma unroll
        for (int nf = 0; nf < 4; nf++) {
            float v0 = c[mf][nf][0], v1 = c[mf][nf][1];
            float v2 = c[mf][nf][2], v3 = c[mf][nf][3];
            op(v0, v1, v2, v3, f.nBase + nf * 8 + 2 * f.et);
            pk[nf][0] = h2u(v0, v1);
            pk[nf][1] = h2u(v2, v3);
        }
        #pragma unroll
        for (int jj = 0; jj < 2; jj++)
            stsm4(base + mf * 4352 + jj * 32,
                  pk[2*jj][0], pk[2*jj][1], pk[2*jj+1][0], pk[2*jj+1][1]);
    }
}

// ============ mega kernel: LN1+QKV+attention+Wo+residual+LN2 ===============
#define QA_SMEM 104448
__global__ __launch_bounds__(256, 2) void k_qkvattn(
    const float* __restrict__ x, const float* __restrict__ lng,
    const float* __restrict__ lnb, const float* __restrict__ bo,
    const float* __restrict__ ln2g, const float* __restrict__ ln2b)
{
    extern __shared__ char dsm[];
    uint32_t sb = smem_u32(dsm);
    const uint32_t R1 = 34816, R2 = 69632;
    int b = blockIdx.x;
    int tid = threadIdx.x, w = tid >> 5;
    Frag f = mkfrag(tid);
    int g8 = f.g8, sel = f.sel, hi8 = f.hi * 8, eg = f.eg, et = f.et;
    int tq0 = w * 16;
    int rowBase = b * 128;
    size_t base = (size_t)rowBase * 128;

    issue_w(sb, R1, g_wq16, 128, tid);
    asm volatile("cp.async.commit_group;" ::: "memory");
    ln_to_smem(dsm, x, lng, lnb, rowBase, tid);

    // ---- Q -> stage R2 -> gmem ----
    asm volatile("cp.async.wait_group 0;" ::: "memory");
    __syncthreads();
    {
        float c[4][4][4];
        #pragma unroll
        for (int mf = 0; mf < 4; mf++)
            #pragma unroll
            for (int nf = 0; nf < 4; nf++)
                #pragma unroll
                for (int j = 0; j < 4; j++) c[mf][nf][j] = 0.f;
        g128_mma(sb, 0, R1, f, c);
        stage_tile<4>(sb, R2, f, c, OpNone());
        __syncthreads();
        issue_w(sb, R1, g_wk16, 128, tid);
        asm volatile("cp.async.commit_group;" ::: "memory");
        #pragma unroll
        for (int i = 0; i < 8; i++) {
            int idx = tid + i * 256;
            int r = idx >> 4, c16 = idx & 15;
            uint4 v = *(const uint4*)(dsm + R2 + r * 272 + c16 * 16);
            *(uint4*)(g_q16 + base + (size_t)r * 128 + c16 * 8) = v;
        }
    }

    // ---- K -> R2 ----
    asm volatile("cp.async.wait_group 0;" ::: "memory");
    __syncthreads();
    {
        float c[4][4][4];
        #pragma unroll
        for (int mf = 0; mf < 4; mf++)
            #pragma unroll
            for (int nf = 0; nf < 4; nf++)
                #pragma unroll
                for (int j = 0; j < 4; j++) c[mf][nf][j] = 0.f;
        g128_mma(sb, 0, R1, f, c);
        stage_tile<4>(sb, R2, f, c, OpNone());
        __syncthreads();
        issue_w(sb, R1, g_wv16, 128, tid);
        asm volatile("cp.async.commit_group;" ::: "memory");
    }

    // ---- V -> R0 ----
    asm volatile("cp.async.wait_group 0;" ::: "memory");
    __syncthreads();
    {
        float c[4][4][4];
        #pragma unroll
        for (int mf = 0; mf < 4; mf++)
            #pragma unroll
            for (int nf = 0; nf < 4; nf++)
                #pragma unroll
                for (int j = 0; j < 4; j++) c[mf][nf][j] = 0.f;
        g128_mma(sb, 0, R1, f, c);
        __syncthreads();
        stage_tile<4>(sb, 0, f, c, OpNone());
        __syncthreads();
    }

    // ---- attention ----
    const __half* qb = g_q16 + base;
    int ra0 = 8 * w + eg;
    int ra1 = 120 - 8 * w + eg;
    int pN = ((127 - 8 * w) >> 4) + 1;

    #pragma unroll
    for (int hh = 0; hh < 4; hh++) {
        float sacc[16][4];
        #pragma unroll
        for (int cn = 0; cn < 16; cn++)
            #pragma unroll
            for (int j = 0; j < 4; j++) sacc[cn][j] = 0.f;

        #pragma unroll
        for (int ks = 0; ks < 2; ks++) {
            int kc = hh * 32 + ks * 16 + 2 * et;
            uint32_t a0 = *(const uint32_t*)(qb + (size_t)ra0 * 128 + kc);
            uint32_t a1 = *(const uint32_t*)(qb + (size_t)ra1 * 128 + kc);
            uint32_t a2 = *(const uint32_t*)(qb + (size_t)ra0 * 128 + kc + 8);
            uint32_t a3 = *(const uint32_t*)(qb + (size_t)ra1 * 128 + kc + 8);
            #pragma unroll
            for (int p = 0; p < 8; p++) {
                if (p < pN) {
                    uint32_t bq[4];
                    ldsm4(bq, sb + R2 + ((p * 16 + g8 + hi8) * 136 + hh * 32 + sel * 8 + ks * 16) * 2);
                    mma_f16(sacc[2 * p],     a0, a1, a2, a3, bq[0], bq[1]);
                    mma_f16(sacc[2 * p + 1], a0, a1, a2, a3, bq[2], bq[3]);
                }
            }
        }

        if (hh == 3) {
            __syncthreads();
            issue_w(sb, R2, g_wo16, 128, tid);
            asm volatile("cp.async.commit_group;" ::: "memory");
        }

        #pragma unroll
        for (int cn = 0; cn < 16; cn++) {
            int c0 = cn * 8 + 2 * et;
            sacc[cn][0] = (c0     <= ra0) ? sacc[cn][0] * SCALE2 : -1e30f;
            sacc[cn][1] = (c0 + 1 <= ra0) ? sacc[cn][1] * SCALE2 : -1e30f;
            sacc[cn][2] = (c0     <= ra1) ? sacc[cn][2] * SCALE2 : -1e30f;
            sacc[cn][3] = (c0 + 1 <= ra1) ? sacc[cn][3] * SCALE2 : -1e30f;
        }

        float m0 = -1e30f, m1 = -1e30f;
        #pragma unroll
        for (int cn = 0; cn < 16; cn++) {
            m0 = fmaxf(m0, fmaxf(sacc[cn][0], sacc[cn][1]));
            m1 = fmaxf(m1, fmaxf(sacc[cn][2], sacc[cn][3]));
        }
        m0 = fmaxf(m0, __shfl_xor_sync(0xffffffffu, m0, 1));
        m0 = fmaxf(m0, __shfl_xor_sync(0xffffffffu, m0, 2));
        m1 = fmaxf(m1, __shfl_xor_sync(0xffffffffu, m1, 1));
        m1 = fmaxf(m1, __shfl_xor_sync(0xffffffffu, m1, 2));

        float l0 = 0.f, l1 = 0.f;
        #pragma unroll
        for (int cn = 0; cn < 16; cn++) {
            sacc[cn][0] = exp2f(sacc[cn][0] - m0);
            sacc[cn][1] = exp2f(sacc[cn][1] - m0);
            sacc[cn][2] = exp2f(sacc[cn][2] - m1);
            sacc[cn][3] = exp2f(sacc[cn][3] - m1);
            l0 += sacc[cn][0] + sacc[cn][1];
            l1 += sacc[cn][2] + sacc[cn][3];
        }
        l0 += __shfl_xor_sync(0xffffffffu, l0, 1);
        l0 += __shfl_xor_sync(0xffffffffu, l0, 2);
        l1 += __shfl_xor_sync(0xffffffffu, l1, 1);
        l1 += __shfl_xor_sync(0xffffffffu, l1, 2);
        float inv0 = 1.f / l0, inv1 = 1.f / l1;

        float oacc[4][4];
        #pragma unroll
        for (int nf = 0; nf < 4; nf++)
            #pragma unroll
            for (int j = 0; j < 4; j++) oacc[nf][j] = 0.f;

        #pragma unroll
        for (int ks = 0; ks < 8; ks++) {
            if (ks < pN) {
                uint32_t a0 = h2u(sacc[2*ks][0],   sacc[2*ks][1]);
                uint32_t a1 = h2u(sacc[2*ks][2],   sacc[2*ks][3]);
                uint32_t a2 = h2u(sacc[2*ks+1][0], sacc[2*ks+1][1]);
                uint32_t a3 = h2u(sacc[2*ks+1][2], sacc[2*ks+1][3]);
                #pragma unroll
                for (int nb = 0; nb < 2; nb++) {
                    uint32_t bq[4];
                    ldsm4t(bq, sb + ((ks * 16 + g8 + sel * 8) * 136 + hh * 32 + nb * 16 + hi8) * 2);
                    mma_f16(oacc[nb * 2],     a0, a1, a2, a3, bq[0], bq[1]);
                    mma_f16(oacc[nb * 2 + 1], a0, a1, a2, a3, bq[2], bq[3]);
                }
            }
        }

        #pragma unroll
        for (int nf = 0; nf < 4; nf++) {
            int col = hh * 32 + nf * 8 + 2 * et;
            *(uint32_t*)(dsm + R1 + ((size_t)ra0 * 136 + col) * 2) =
                h2u(oacc[nf][0] * inv0, oacc[nf][1] * inv0);
            *(uint32_t*)(dsm + R1 + ((size_t)ra1 * 136 + col) * 2) =
                h2u(oacc[nf][2] * inv1, oacc[nf][3] * inv1);
        }
    }

    asm volatile("cp.async.wait_group 0;" ::: "memory");
    __syncthreads();

    // ---- Wo GEMM ----
    float c[16][4];
    #pragma unroll
    for (int nf = 0; nf < 16; nf++)
        #pragma unroll
        for (int j = 0; j < 4; j++) c[nf][j] = 0.f;

    uint32_t aB = sb + R1 + ((tq0 + g8 + sel * 8) * 136 + hi8) * 2;
    uint32_t bB = sb + R2 + ((g8 + hi8) * 136 + sel * 8) * 2;
    #pragma unroll
    for (int ks = 0; ks < 8; ks++) {
        uint32_t a[4];
        ldsm4(a, aB + ks * 32);
        #pragma unroll
        for (int p = 0; p < 8; p++) {
            uint32_t bq[4];
            ldsm4(bq, bB + p * 4352 + ks * 32);
            mma_f16(c[2 * p],     a[0], a[1], a[2], a[3], bq[0], bq[1]);
            mma_f16(c[2 * p + 1], a[0], a[1], a[2], a[3], bq[2], bq[3]);
        }
    }

    // ---- epilogue: x2 = c + bo + x  (write fp32)  +  LN2 -> h2 (fp16) ----
    int r0 = tq0 + eg, r1 = r0 + 8;
    int grow0 = rowBase + r0, grow1 = rowBase + r1;

    float s0 = 0.f, q0 = 0.f, s1 = 0.f, q1 = 0.f;
    #pragma unroll
    for (int nf = 0; nf < 16; nf++) {
        int col = nf * 8 + 2 * et;
        float2 bb = *(const float2*)(bo + col);
        float2 xv0 = *(const float2*)(x + (size_t)grow0 * 128 + col);
        float2 xv1 = *(const float2*)(x + (size_t)grow1 * 128 + col);
        c[nf][0] += bb.x + xv0.x; c[nf][1] += bb.y + xv0.y;
        c[nf][2] += bb.x + xv1.x; c[nf][3] += bb.y + xv1.y;
        *(float2*)(g_x2 + (size_t)grow0 * 128 + col) = make_float2(c[nf][0], c[nf][1]);
        *(float2*)(g_x2 + (size_t)grow1 * 128 + col) = make_float2(c[nf][2], c[nf][3]);
        s0 += c[nf][0] + c[nf][1];  q0 += c[nf][0]*c[nf][0] + c[nf][1]*c[nf][1];
        s1 += c[nf][2] + c[nf][3];  q1 += c[nf][2]*c[nf][2] + c[nf][3]*c[nf][3];
    }
    // quad reduce (row spans lanes eg*4 .. eg*4+3)
    s0 += __shfl_xor_sync(0xffffffffu, s0, 1); s0 += __shfl_xor_sync(0xffffffffu, s0, 2);
    q0 += __shfl_xor_sync(0xffffffffu, q0, 1); q0 += __shfl_xor_sync(0xffffffffu, q0, 2);
    s1 += __shfl_xor_sync(0xffffffffu, s1, 1); s1 += __shfl_xor_sync(0xffffffffu, s1, 2);
    q1 += __shfl_xor_sync(0xffffffffu, q1, 1); q1 += __shfl_xor_sync(0xffffffffu, q1, 2);
    float mu0 = s0 * (1.f/128.f), mu1 = s1 * (1.f/128.f);
    float rs0 = rsqrtf(q0 * (1.f/128.f) - mu0*mu0 + 1e-5f);
    float rs1 = rsqrtf(q1 * (1.f/128.f) - mu1*mu1 + 1e-5f);

    #pragma unroll
    for (int nf = 0; nf < 16; nf++) {
        int col = nf * 8 + 2 * et;
        float2 gg = *(const float2*)(ln2g + col);
        float2 bb2 = *(const float2*)(ln2b + col);
        *(uint32_t*)(g_h16 + (size_t)grow0 * 128 + col) =
            h2u((c[nf][0]-mu0)*rs0*gg.x + bb2.x, (c[nf][1]-mu0)*rs0*gg.y + bb2.y);
        *(uint32_t*)(g_h16 + (size_t)grow1 * 128 + col) =
            h2u((c[nf][2]-mu1)*rs1*gg.x + bb2.x, (c[nf][3]-mu1)*rs1*gg.y + bb2.y);
    }
}

// ---------------- fused FFN (M=64, occ 2; A = precomputed LN2 fp16) --------
#define FFN_SMEM 104448
__global__ __launch_bounds__(256, 2) void k_ffn64(
    const float* __restrict__ b1, const float* __restrict__ b2,
    float* __restrict__ out)
{
    extern __shared__ char dsm[];
    uint32_t sb = smem_u32(dsm);
    const uint32_t FFO = 17408, W1OFF = 34816, W2OFF = 69632;
    int tid = threadIdx.x;
    int rowBase = blockIdx.x * 64;
    Frag f = mkfrag64(tid);

    // group0 = A + W1(0); group1 = W2(0)
    issue_a64(sb, g_h16 + (size_t)rowBase * 128, tid);
    issue_w(sb, W1OFF, g_w116, 128, tid);
    asm volatile("cp.async.commit_group;" ::: "memory");
    issue_w(sb, W2OFF, g_w216, 512, tid);
    asm volatile("cp.async.commit_group;" ::: "memory");

    float c2[2][4][4];
    #pragma unroll
    for (int mf = 0; mf < 2; mf++)
        #pragma unroll
        for (int nf = 0; nf < 4; nf++)
            #pragma unroll
            for (int j = 0; j < 4; j++) c2[mf][nf][j] = 0.f;

    #pragma unroll
    for (int blk = 0; blk < 4; blk++) {
        asm volatile("cp.async.wait_group 1;" ::: "memory");
        __syncthreads();

        float c1[2][4][4];
        #pragma unroll
        for (int mf = 0; mf < 2; mf++)
            #pragma unroll
            for (int nf = 0; nf < 4; nf++)
                #pragma unroll
                for (int j = 0; j < 4; j++) c1[mf][nf][j] = 0.f;
        g64_mma(sb, 0, W1OFF, f, c1);
        __syncthreads();

        if (blk < 3) {
            issue_w(sb, W1OFF, g_w116 + (size_t)(blk + 1) * 128 * 128, 128, tid);
            asm volatile("cp.async.commit_group;" ::: "memory");
        }

        OpBiasRelu op; op.b1b = b1 + blk * 128;
        stage_tile<2>(sb, FFO, f, c1, op);

        if (blk < 3) asm volatile("cp.async.wait_group 1;" ::: "memory");
        else         asm volatile("cp.async.wait_group 0;" ::: "memory");
        __syncthreads();

        g64_mma(sb, FFO, W2OFF, f, c2);
        __syncthreads();

        if (blk < 3) {
            issue_w(sb, W2OFF, g_w216 + (size_t)(blk + 1) * 128, 512, tid);
            asm volatile("cp.async.commit_group;" ::: "memory");
        }
    }

    #pragma unroll
    for (int mf = 0; mf < 2; mf++)
        #pragma unroll
        for (int rr = 0; rr < 2; rr++) {
            int row = rowBase + f.mBase + mf * 16 + f.eg + rr * 8;
            #pragma unroll
            for (int nf = 0; nf < 4; nf++) {
                int col = f.nBase + nf * 8 + 2 * f.et;
                float2 bb = *(const float2*)(b2 + col);
                float2 rv = *(const float2*)(g_x2 + (size_t)row * 128 + col);
                *(float2*)(out + (size_t)row * 128 + col) =
                    make_float2(c2[mf][nf][rr * 2]     + bb.x + rv.x,
                                c2[mf][nf][rr * 2 + 1] + bb.y + rv.y);
            }
        }
}

// ---------------- launch ----------------
extern "C" void kernel_launch(void* const* d_in, const int* in_sizes, int n_in,
                              void* d_out, int out_size)
{
    const float* x     = (const float*)d_in[0];
    const float* ln1_g = (const float*)d_in[1];
    const float* ln1_b = (const float*)d_in[2];
    const float* Wq    = (const float*)d_in[3];
    const float* Wk    = (const float*)d_in[4];
    const float* Wv    = (const float*)d_in[5];
    const float* Wo    = (const float*)d_in[6];
    const float* bo    = (const float*)d_in[7];
    const float* ln2_g = (const float*)d_in[8];
    const float* ln2_b = (const float*)d_in[9];
    const float* W1    = (const float*)d_in[10];
    const float* b1    = (const float*)d_in[11];
    const float* W2    = (const float*)d_in[12];
    const float* b2    = (const float*)d_in[13];
    float* out = (float*)d_out;

    static bool attrs_set = false;
    if (!attrs_set) {
        cudaFuncSetAttribute(k_qkvattn, cudaFuncAttributeMaxDynamicSharedMemorySize, QA_SMEM);
        cudaFuncSetAttribute(k_ffn64,   cudaFuncAttributeMaxDynamicSharedMemorySize, FFN_SMEM);
        attrs_set = true;
    }

    // 0) weights -> fp16 (vectorized)
    cvt6<<<dim3(64, 6), 256>>>(Wq, Wk, Wv, Wo, W1, W2);

    // 1) LN1 + QKV + attention + Wo + residual + LN2 -> x2, h2
    k_qkvattn<<<Bv, 256, QA_SMEM>>>(x, ln1_g, ln1_b, bo, ln2_g, ln2_b);

    // 2) FFN1 + FFN2 + residual
    k_ffn64<<<BT / 64, 256, FFN_SMEM>>>(b1, b2, out);
}